// round 5
// baseline (speedup 1.0000x reference)
#include <cuda_runtime.h>
#include <math.h>
#include <stdint.h>

#define N_NODES 4096
#define FIN 20
#define H 4
#define D 64
#define TILE_C 64
#define ROWS_PER_BLK 32

// double-buffered tile (floats): whs[4][64][64]=16384, adj[32][65]=2080, fd[4][64]=256
#define BUF_FLOATS (16384 + 2080 + 256)
#define P_STRIDE 68
#define P_OFF (2 * BUF_FLOATS)                  // 37440
#define ROWL_OFF (P_OFF + H * 32 * P_STRIDE)    // 37440 + 8704 = 46144
#define ATTN_FLOATS (ROWL_OFF + 128)            // 46272
#define ATTN_SMEM (ATTN_FLOATS * 4)             // 185088 B
#define WH1_SMEM ((64 * 256 + 256 * 64) * 4)    // 131072 B

// ---------------- device scratch ----------------
__device__ float g_Wh[H * N_NODES * D];
__device__ float g_fs[H * N_NODES];
__device__ float g_fd[H * N_NODES];
__device__ float g_maxfd[H];
__device__ float g_h1[N_NODES * H * D];

// ---------------- helpers ----------------
__device__ __forceinline__ float wsum(float v) {
#pragma unroll
    for (int s = 16; s > 0; s >>= 1) v += __shfl_xor_sync(0xffffffffu, v, s);
    return v;
}
__device__ __forceinline__ unsigned long long pack2(float x) {
    unsigned long long r;
    asm("mov.b64 %0, {%1, %1};" : "=l"(r) : "f"(x));
    return r;
}
__device__ __forceinline__ void fma2(unsigned long long& d, unsigned long long a,
                                     unsigned long long b) {
    asm("fma.rn.f32x2 %0, %1, %2, %0;" : "+l"(d) : "l"(a), "l"(b));
}
__device__ __forceinline__ float elu_f(float x) { return x > 0.f ? x : expm1f(x); }

__device__ __forceinline__ void cp16(uint32_t s, const void* g) {
    asm volatile("cp.async.cg.shared.global [%0], [%1], 16;" :: "r"(s), "l"(g));
}
__device__ __forceinline__ void cp4(uint32_t s, const void* g) {
    asm volatile("cp.async.ca.shared.global [%0], [%1], 4;" :: "r"(s), "l"(g));
}
__device__ __forceinline__ void cp_commit() { asm volatile("cp.async.commit_group;"); }
__device__ __forceinline__ void cp_wait0() { asm volatile("cp.async.wait_group 0;"); }

// ---------------- layer-0 projection ----------------
__global__ void k_wh0(const float* __restrict__ x, const float* __restrict__ W0,
                      const float* __restrict__ a0) {
    int h = blockIdx.y, o = threadIdx.x;
    int n0 = blockIdx.x * 8;
    __shared__ float xs[8][FIN];
    for (int idx = o; idx < 8 * FIN; idx += 64)
        xs[idx / FIN][idx % FIN] = x[n0 * FIN + idx];
    __syncthreads();
    float wh[8] = {0.f, 0.f, 0.f, 0.f, 0.f, 0.f, 0.f, 0.f};
#pragma unroll
    for (int f = 0; f < FIN; f++) {
        float w = W0[(h * FIN + f) * D + o];
#pragma unroll
        for (int r = 0; r < 8; r++) wh[r] += xs[r][f] * w;
    }
#pragma unroll
    for (int r = 0; r < 8; r++) g_Wh[(h * N_NODES + n0 + r) * D + o] = wh[r];

    float as = __ldg(a0 + h * 2 * D + o), ad = __ldg(a0 + h * 2 * D + D + o);
    __shared__ float rb[2][2][8];
    int w = o >> 5, lane = o & 31;
#pragma unroll
    for (int r = 0; r < 8; r++) {
        float ps = wsum(wh[r] * as);
        float pd = wsum(wh[r] * ad);
        if (lane == 0) { rb[0][w][r] = ps; rb[1][w][r] = pd; }
    }
    __syncthreads();
    if (o < 8) {
        g_fs[h * N_NODES + n0 + o] = rb[0][0][o] + rb[0][1][o];
        g_fd[h * N_NODES + n0 + o] = rb[1][0][o] + rb[1][1][o];
    }
}

// ---------------- layer-1 projection (smem-staged) ----------------
// grid (64, H), block 256. CTA = 64 rows x 64 cols; thread = 8 rows x 2 cols.
__global__ void __launch_bounds__(256)
k_wh1(const float* __restrict__ W1, const float* __restrict__ a1) {
    extern __shared__ float sm[];
    float* hs = sm;            // [64][256]
    float* ws = sm + 16384;    // [256][64]
    int h = blockIdx.y;
    int n0 = blockIdx.x * 64;
    int tid = threadIdx.x;
    int lane = tid & 31, rq = tid >> 5;

    const float4* hsrc = reinterpret_cast<const float4*>(g_h1 + (size_t)n0 * (H * D));
    const float4* wsrc = reinterpret_cast<const float4*>(W1 + (size_t)h * (H * D) * D);
    float4* hd = reinterpret_cast<float4*>(hs);
    float4* wd = reinterpret_cast<float4*>(ws);
#pragma unroll
    for (int v = tid; v < 4096; v += 256) { hd[v] = hsrc[v]; wd[v] = wsrc[v]; }
    __syncthreads();

    unsigned long long acc[8];
#pragma unroll
    for (int r = 0; r < 8; r++) acc[r] = 0ull;

    const float* hb = hs + (rq * 8) * (H * D);
#pragma unroll 4
    for (int f = 0; f < H * D; f++) {
        unsigned long long w2 =
            *reinterpret_cast<const unsigned long long*>(ws + f * D + 2 * lane);
#pragma unroll
        for (int r = 0; r < 8; r++) fma2(acc[r], pack2(hb[r * (H * D) + f]), w2);
    }

#pragma unroll
    for (int r = 0; r < 8; r++) {
        float2 t = *reinterpret_cast<float2*>(&acc[r]);
        *reinterpret_cast<float2*>(g_Wh + ((size_t)(h * N_NODES + n0 + rq * 8 + r)) * D +
                                   2 * lane) = t;
    }

    float2 as2 = *reinterpret_cast<const float2*>(a1 + h * 2 * D + 2 * lane);
    float2 ad2 = *reinterpret_cast<const float2*>(a1 + h * 2 * D + D + 2 * lane);
    __shared__ float rb[2][8][8];
#pragma unroll
    for (int r = 0; r < 8; r++) {
        float2 t = *reinterpret_cast<float2*>(&acc[r]);
        float ps = wsum(t.x * as2.x + t.y * as2.y);
        float pd = wsum(t.x * ad2.x + t.y * ad2.y);
        if (lane == 0) { rb[0][rq][r] = ps; rb[1][rq][r] = pd; }
    }
    __syncthreads();
    if (tid < 64) {
        g_fs[h * N_NODES + n0 + tid] = rb[0][tid >> 3][tid & 7];
    } else if (tid < 128) {
        int r = tid - 64;
        g_fd[h * N_NODES + n0 + r] = rb[1][r >> 3][r & 7];
    }
}

// ---------------- per-head max of fd ----------------
__global__ void k_maxfd() {
    int h = blockIdx.x;
    float mx = -1e30f;
    for (int j = threadIdx.x; j < N_NODES; j += 256)
        mx = fmaxf(mx, g_fd[h * N_NODES + j]);
#pragma unroll
    for (int s = 16; s > 0; s >>= 1) mx = fmaxf(mx, __shfl_xor_sync(0xffffffffu, mx, s));
    __shared__ float smx[8];
    if ((threadIdx.x & 31) == 0) smx[threadIdx.x >> 5] = mx;
    __syncthreads();
    if (threadIdx.x == 0) {
        float r = smx[0];
#pragma unroll
        for (int i = 1; i < 8; i++) r = fmaxf(r, smx[i]);
        g_maxfd[h] = r;
    }
}

// ---------------- async tile stage (256 threads) ----------------
__device__ __forceinline__ void stage_tile(float* buf, int rowbase, int jbase,
                                           const int* __restrict__ adj, int tid) {
    uint32_t sw = (uint32_t)__cvta_generic_to_shared(buf);
    uint32_t sa = sw + 16384u * 4u;
    uint32_t sf = sa + 2080u * 4u;
    const char* Wg = (const char*)g_Wh;
#pragma unroll
    for (int v = tid; v < 4096; v += 256) {
        int hh = v >> 10;
        int j = (v >> 4) & 63;
        int c = v & 15;
        cp16(sw + (uint32_t)v * 16u,
             Wg + ((size_t)((hh * N_NODES + jbase + j) * 16 + c)) * 16u);
    }
#pragma unroll
    for (int idx = tid; idx < 2048; idx += 256) {
        int r = idx >> 6, c = idx & 63;
        cp4(sa + (uint32_t)(r * 65 + c) * 4u,
            adj + (size_t)(rowbase + r) * N_NODES + jbase + c);
    }
    {
        int hh = tid >> 6, j = tid & 63;
        cp4(sf + (uint32_t)tid * 4u, g_fd + hh * N_NODES + jbase + j);
    }
    cp_commit();
}

// ---------------- fused GAT attention: P-stage + register-tiled GEMM ----------------
// 8 warps: warp w -> head (w&3), row-half (w>>2). Warp owns 16 rows.
// P-stage lanes: (prow = lane>>1, jh = lane&1). GEMM lanes: (lr = lane>>3, lc = lane&7),
// thread tile = 4 rows x 8 cols.
template <bool AVG>
__global__ void __launch_bounds__(256)
k_attn(const int* __restrict__ adj, float* __restrict__ out) {
    extern __shared__ float smem[];
    float* Pbase = smem + P_OFF;
    float* rowl = smem + ROWL_OFF;

    int tid = threadIdx.x;
    int lane = tid & 31;
    int w = tid >> 5;
    int h = w & 3;
    int half = w >> 2;
    int rowbase = blockIdx.x * ROWS_PER_BLK;

    // P-stage persistent state
    int prow = half * 16 + (lane >> 1);
    int jh = lane & 1;
    float fs_p = g_fs[h * N_NODES + rowbase + prow];
    float m_p = fs_p + g_maxfd[h];
    m_p = fmaxf(m_p, 0.2f * m_p);
    float l_acc = 0.f;
    float* Pw = Pbase + (h * 32 + prow) * P_STRIDE;

    // GEMM persistent state
    int lr = lane >> 3, lc = lane & 7;
    unsigned long long acc[16];
#pragma unroll
    for (int c = 0; c < 16; c++) acc[c] = 0ull;

    stage_tile(smem, rowbase, 0, adj, tid);
    cp_wait0();
    __syncthreads();

    for (int jb = 0; jb < N_NODES / TILE_C; jb++) {
        float* cur = smem + (jb & 1) * BUF_FLOATS;
        float* nxt = smem + ((jb + 1) & 1) * BUF_FLOATS;
        if (jb + 1 < N_NODES / TILE_C)
            stage_tile(nxt, rowbase, (jb + 1) * TILE_C, adj, tid);

        const int* adjs = (const int*)(cur + 16384);
        const float* fds = cur + 16384 + 2080;

        // ---- P-stage: scores for this warp's 16 rows ----
#pragma unroll 8
        for (int jj = 0; jj < 32; jj++) {
            int j = jh * 32 + jj;
            int a = adjs[prow * 65 + j];
            float e = fs_p + fds[h * 64 + j];
            e = fmaxf(e, 0.2f * e);
            float p = a ? __expf(e - m_p) : 0.f;
            l_acc += p;
            Pw[j] = p;
        }
        __syncwarp();

        // ---- GEMM: 16 rows x 64 cols, thread tile 4x8 ----
        const float* whb = cur + (h * 64) * 64 + lc * 8;
        const float* Pg = Pbase + (h * 32 + half * 16 + lr * 4) * P_STRIDE;
#pragma unroll 4
        for (int j4 = 0; j4 < 16; j4++) {
            float4 pr0 = *reinterpret_cast<const float4*>(Pg + 0 * P_STRIDE + j4 * 4);
            float4 pr1 = *reinterpret_cast<const float4*>(Pg + 1 * P_STRIDE + j4 * 4);
            float4 pr2 = *reinterpret_cast<const float4*>(Pg + 2 * P_STRIDE + j4 * 4);
            float4 pr3 = *reinterpret_cast<const float4*>(Pg + 3 * P_STRIDE + j4 * 4);
#pragma unroll
            for (int dj = 0; dj < 4; dj++) {
                int j = j4 * 4 + dj;
                ulonglong2 w01 =
                    *reinterpret_cast<const ulonglong2*>(whb + j * 64);
                ulonglong2 w23 =
                    *reinterpret_cast<const ulonglong2*>(whb + j * 64 + 4);
                float p0 = dj == 0 ? pr0.x : dj == 1 ? pr0.y : dj == 2 ? pr0.z : pr0.w;
                float p1 = dj == 0 ? pr1.x : dj == 1 ? pr1.y : dj == 2 ? pr1.z : pr1.w;
                float p2v = dj == 0 ? pr2.x : dj == 1 ? pr2.y : dj == 2 ? pr2.z : pr2.w;
                float p3 = dj == 0 ? pr3.x : dj == 1 ? pr3.y : dj == 2 ? pr3.z : pr3.w;
                unsigned long long q0 = pack2(p0), q1 = pack2(p1);
                unsigned long long q2 = pack2(p2v), q3 = pack2(p3);
                fma2(acc[0], w01.x, q0); fma2(acc[1], w01.y, q0);
                fma2(acc[2], w23.x, q0); fma2(acc[3], w23.y, q0);
                fma2(acc[4], w01.x, q1); fma2(acc[5], w01.y, q1);
                fma2(acc[6], w23.x, q1); fma2(acc[7], w23.y, q1);
                fma2(acc[8], w01.x, q2); fma2(acc[9], w01.y, q2);
                fma2(acc[10], w23.x, q2); fma2(acc[11], w23.y, q2);
                fma2(acc[12], w01.x, q3); fma2(acc[13], w01.y, q3);
                fma2(acc[14], w23.x, q3); fma2(acc[15], w23.y, q3);
            }
        }
        cp_wait0();
        __syncthreads();
    }

    // softmax denominators: combine jh halves, publish per row (warp-local)
    l_acc += __shfl_xor_sync(0xffffffffu, l_acc, 1);
    if ((lane & 1) == 0) rowl[h * 32 + prow] = l_acc;
    __syncwarp();

    if (AVG) __syncthreads();  // redB aliases P: wait until all warps done reading P

    float* redB = Pbase;  // [H][32][64] reuse
#pragma unroll
    for (int r = 0; r < 4; r++) {
        int row = half * 16 + lr * 4 + r;
        float inv = 1.0f / fmaxf(rowl[h * 32 + row], 1e-30f);
        float v[8];
#pragma unroll
        for (int k = 0; k < 4; k++) {
            float2 t = *reinterpret_cast<float2*>(&acc[r * 4 + k]);
            v[2 * k] = elu_f(t.x * inv);
            v[2 * k + 1] = elu_f(t.y * inv);
        }
        if (!AVG) {
            float* dst = g_h1 + (size_t)(rowbase + row) * (H * D) + h * D + lc * 8;
            *reinterpret_cast<float4*>(dst) = make_float4(v[0], v[1], v[2], v[3]);
            *reinterpret_cast<float4*>(dst + 4) = make_float4(v[4], v[5], v[6], v[7]);
        } else {
            float* dst = redB + (h * 32 + row) * 64 + lc * 8;
            *reinterpret_cast<float4*>(dst) = make_float4(v[0], v[1], v[2], v[3]);
            *reinterpret_cast<float4*>(dst + 4) = make_float4(v[4], v[5], v[6], v[7]);
        }
    }

    if (AVG) {
        __syncthreads();
        for (int idx = tid; idx < ROWS_PER_BLK * D; idx += 256) {
            int r = idx >> 6, k = idx & 63;
            float s = 0.25f * (redB[(0 * 32 + r) * 64 + k] + redB[(1 * 32 + r) * 64 + k] +
                               redB[(2 * 32 + r) * 64 + k] + redB[(3 * 32 + r) * 64 + k]);
            out[(rowbase + r) * D + k] = s;
        }
    }
}

// ---------------- launch ----------------
extern "C" void kernel_launch(void* const* d_in, const int* in_sizes, int n_in,
                              void* d_out, int out_size) {
    const float* x = (const float*)d_in[0];
    const int* adj = (const int*)d_in[1];
    const float* W0 = (const float*)d_in[2];
    const float* a0 = (const float*)d_in[3];
    const float* W1 = (const float*)d_in[4];
    const float* a1 = (const float*)d_in[5];
    float* out = (float*)d_out;

    cudaFuncSetAttribute(k_attn<false>, cudaFuncAttributeMaxDynamicSharedMemorySize,
                         ATTN_SMEM);
    cudaFuncSetAttribute(k_attn<true>, cudaFuncAttributeMaxDynamicSharedMemorySize,
                         ATTN_SMEM);
    cudaFuncSetAttribute(k_wh1, cudaFuncAttributeMaxDynamicSharedMemorySize, WH1_SMEM);

    // layer 0
    k_wh0<<<dim3(N_NODES / 8, H), 64>>>(x, W0, a0);
    k_maxfd<<<H, 256>>>();
    k_attn<false><<<N_NODES / ROWS_PER_BLK, 256, ATTN_SMEM>>>(adj, nullptr);

    // layer 1
    k_wh1<<<dim3(N_NODES / 64, H), 256, WH1_SMEM>>>(W1, a1);
    k_maxfd<<<H, 256>>>();
    k_attn<true><<<N_NODES / ROWS_PER_BLK, 256, ATTN_SMEM>>>(adj, out);
}

// round 6
// speedup vs baseline: 1.5805x; 1.5805x over previous
#include <cuda_runtime.h>
#include <math.h>
#include <stdint.h>

#define N_NODES 4096
#define FIN 20
#define H 4
#define D 64
#define TILE_C 64
#define ROWS_PER_BLK 32

// double-buffered tile (floats): whs[4][64][64]=16384, adj[32][65]=2080, fd[4][64]=256
#define BUF_FLOATS (16384 + 2080 + 256)
#define ATTN_SMEM (2 * BUF_FLOATS * 4)           // 149760 B
// epilogue overlays (within the 2*BUF_FLOATS region):
#define PART_STRIDE 68
#define LBUF_OFF (3 * 128 * PART_STRIDE)          // 26112
#define REDB_OFF (LBUF_OFF + 384)                 // 26496 (+8192 = 34688 <= 37440)
#define WH1_SMEM ((64 * 256 + 256 * 64) * 4)      // 131072 B

// ---------------- device scratch ----------------
__device__ float g_Wh[H * N_NODES * D];
__device__ float g_fs[H * N_NODES];
__device__ float g_fd[H * N_NODES];
__device__ float g_maxfd[H];
__device__ float g_h1[N_NODES * H * D];

// ---------------- helpers ----------------
__device__ __forceinline__ float wsum(float v) {
#pragma unroll
    for (int s = 16; s > 0; s >>= 1) v += __shfl_xor_sync(0xffffffffu, v, s);
    return v;
}
__device__ __forceinline__ unsigned long long pack2(float x) {
    unsigned long long r;
    asm("mov.b64 %0, {%1, %1};" : "=l"(r) : "f"(x));
    return r;
}
__device__ __forceinline__ void fma2(unsigned long long& d, unsigned long long a,
                                     unsigned long long b) {
    asm("fma.rn.f32x2 %0, %1, %2, %0;" : "+l"(d) : "l"(a), "l"(b));
}
__device__ __forceinline__ float elu_f(float x) { return x > 0.f ? x : expm1f(x); }

__device__ __forceinline__ void cp16(uint32_t s, const void* g) {
    asm volatile("cp.async.cg.shared.global [%0], [%1], 16;" :: "r"(s), "l"(g));
}
__device__ __forceinline__ void cp4(uint32_t s, const void* g) {
    asm volatile("cp.async.ca.shared.global [%0], [%1], 4;" :: "r"(s), "l"(g));
}
__device__ __forceinline__ void cp_commit() { asm volatile("cp.async.commit_group;"); }
__device__ __forceinline__ void cp_wait0() { asm volatile("cp.async.wait_group 0;"); }

// ---------------- layer-0 projection ----------------
__global__ void k_wh0(const float* __restrict__ x, const float* __restrict__ W0,
                      const float* __restrict__ a0) {
    int h = blockIdx.y, o = threadIdx.x;
    int n0 = blockIdx.x * 8;
    __shared__ float xs[8][FIN];
    for (int idx = o; idx < 8 * FIN; idx += 64)
        xs[idx / FIN][idx % FIN] = x[n0 * FIN + idx];
    __syncthreads();
    float wh[8] = {0.f, 0.f, 0.f, 0.f, 0.f, 0.f, 0.f, 0.f};
#pragma unroll
    for (int f = 0; f < FIN; f++) {
        float w = W0[(h * FIN + f) * D + o];
#pragma unroll
        for (int r = 0; r < 8; r++) wh[r] += xs[r][f] * w;
    }
#pragma unroll
    for (int r = 0; r < 8; r++) g_Wh[(h * N_NODES + n0 + r) * D + o] = wh[r];

    float as = __ldg(a0 + h * 2 * D + o), ad = __ldg(a0 + h * 2 * D + D + o);
    __shared__ float rb[2][2][8];
    int w = o >> 5, lane = o & 31;
#pragma unroll
    for (int r = 0; r < 8; r++) {
        float ps = wsum(wh[r] * as);
        float pd = wsum(wh[r] * ad);
        if (lane == 0) { rb[0][w][r] = ps; rb[1][w][r] = pd; }
    }
    __syncthreads();
    if (o < 8) {
        g_fs[h * N_NODES + n0 + o] = rb[0][0][o] + rb[0][1][o];
        g_fd[h * N_NODES + n0 + o] = rb[1][0][o] + rb[1][1][o];
    }
}

// ---------------- layer-1 projection (smem-staged, unchanged: 23.5us) ----------------
__global__ void __launch_bounds__(256)
k_wh1(const float* __restrict__ W1, const float* __restrict__ a1) {
    extern __shared__ float sm[];
    float* hs = sm;            // [64][256]
    float* ws = sm + 16384;    // [256][64]
    int h = blockIdx.y;
    int n0 = blockIdx.x * 64;
    int tid = threadIdx.x;
    int lane = tid & 31, rq = tid >> 5;

    const float4* hsrc = reinterpret_cast<const float4*>(g_h1 + (size_t)n0 * (H * D));
    const float4* wsrc = reinterpret_cast<const float4*>(W1 + (size_t)h * (H * D) * D);
    float4* hd = reinterpret_cast<float4*>(hs);
    float4* wd = reinterpret_cast<float4*>(ws);
#pragma unroll
    for (int v = tid; v < 4096; v += 256) { hd[v] = hsrc[v]; wd[v] = wsrc[v]; }
    __syncthreads();

    unsigned long long acc[8];
#pragma unroll
    for (int r = 0; r < 8; r++) acc[r] = 0ull;

    const float* hb = hs + (rq * 8) * (H * D);
#pragma unroll 4
    for (int f = 0; f < H * D; f++) {
        unsigned long long w2 =
            *reinterpret_cast<const unsigned long long*>(ws + f * D + 2 * lane);
#pragma unroll
        for (int r = 0; r < 8; r++) fma2(acc[r], pack2(hb[r * (H * D) + f]), w2);
    }

#pragma unroll
    for (int r = 0; r < 8; r++) {
        float2 t = *reinterpret_cast<float2*>(&acc[r]);
        *reinterpret_cast<float2*>(g_Wh + ((size_t)(h * N_NODES + n0 + rq * 8 + r)) * D +
                                   2 * lane) = t;
    }

    float2 as2 = *reinterpret_cast<const float2*>(a1 + h * 2 * D + 2 * lane);
    float2 ad2 = *reinterpret_cast<const float2*>(a1 + h * 2 * D + D + 2 * lane);
    __shared__ float rb[2][8][8];
#pragma unroll
    for (int r = 0; r < 8; r++) {
        float2 t = *reinterpret_cast<float2*>(&acc[r]);
        float ps = wsum(t.x * as2.x + t.y * as2.y);
        float pd = wsum(t.x * ad2.x + t.y * ad2.y);
        if (lane == 0) { rb[0][rq][r] = ps; rb[1][rq][r] = pd; }
    }
    __syncthreads();
    if (tid < 64) {
        g_fs[h * N_NODES + n0 + tid] = rb[0][tid >> 3][tid & 7];
    } else if (tid < 128) {
        int r = tid - 64;
        g_fd[h * N_NODES + n0 + r] = rb[1][r >> 3][r & 7];
    }
}

// ---------------- per-head max of fd ----------------
__global__ void k_maxfd() {
    int h = blockIdx.x;
    float mx = -1e30f;
    for (int j = threadIdx.x; j < N_NODES; j += 256)
        mx = fmaxf(mx, g_fd[h * N_NODES + j]);
#pragma unroll
    for (int s = 16; s > 0; s >>= 1) mx = fmaxf(mx, __shfl_xor_sync(0xffffffffu, mx, s));
    __shared__ float smx[8];
    if ((threadIdx.x & 31) == 0) smx[threadIdx.x >> 5] = mx;
    __syncthreads();
    if (threadIdx.x == 0) {
        float r = smx[0];
#pragma unroll
        for (int i = 1; i < 8; i++) r = fmaxf(r, smx[i]);
        g_maxfd[h] = r;
    }
}

// ---------------- async tile stage (512 threads) ----------------
__device__ __forceinline__ void stage_tile(float* buf, int rowbase, int jbase,
                                           const int* __restrict__ adj, int tid) {
    uint32_t sw = (uint32_t)__cvta_generic_to_shared(buf);
    uint32_t sa = sw + 16384u * 4u;
    uint32_t sf = sa + 2080u * 4u;
    const char* Wg = (const char*)g_Wh;
#pragma unroll
    for (int v = tid; v < 4096; v += 512) {
        int hh = v >> 10;
        int j = (v >> 4) & 63;
        int c = v & 15;
        cp16(sw + (uint32_t)v * 16u,
             Wg + ((size_t)((hh * N_NODES + jbase + j) * 16 + c)) * 16u);
    }
#pragma unroll
    for (int idx = tid; idx < 2048; idx += 512) {
        int r = idx >> 6, c = idx & 63;
        cp4(sa + (uint32_t)(r * 65 + c) * 4u,
            adj + (size_t)(rowbase + r) * N_NODES + jbase + c);
    }
    if (tid < 256) {
        int hh = tid >> 6, j = tid & 63;
        cp4(sf + (uint32_t)tid * 4u, g_fd + hh * N_NODES + jbase + j);
    }
    cp_commit();
}

// ---------------- fused flash-style GAT attention ----------------
// 512 threads = 16 warps: warp w -> head (w&3), j-quarter (w>>2). lane = row.
// Four j-quarter partial sums combine exactly (fixed shift m) in epilogue.
template <bool AVG>
__global__ void __launch_bounds__(512)
k_attn(const int* __restrict__ adj, float* __restrict__ out) {
    extern __shared__ float smem[];

    int tid = threadIdx.x;
    int lane = tid & 31;
    int w = tid >> 5;
    int h = w & 3;
    int g = w >> 2;                    // j-quarter 0..3
    int rowbase = blockIdx.x * ROWS_PER_BLK;
    int i = rowbase + lane;

    float my_fs = g_fs[h * N_NODES + i];
    float m = my_fs + g_maxfd[h];
    m = fmaxf(m, 0.2f * m);

    unsigned long long acc2[32];
#pragma unroll
    for (int c = 0; c < 32; c++) acc2[c] = 0ull;
    float l = 0.f;

    stage_tile(smem, rowbase, 0, adj, tid);
    cp_wait0();
    __syncthreads();

    int j0 = g * 16;
    for (int jb = 0; jb < N_NODES / TILE_C; jb++) {
        float* cur = smem + (jb & 1) * BUF_FLOATS;
        float* nxt = smem + ((jb + 1) & 1) * BUF_FLOATS;
        if (jb + 1 < N_NODES / TILE_C)
            stage_tile(nxt, rowbase, (jb + 1) * TILE_C, adj, tid);

        const int* adjs = (const int*)(cur + 16384);
        const float* fds = cur + 16384 + 2080;
        const float* whs = cur;

#pragma unroll 2
        for (int jj = 0; jj < 16; jj++) {
            int j = j0 + jj;
            int a = adjs[lane * 65 + j];
            float e = my_fs + fds[h * 64 + j];
            e = fmaxf(e, 0.2f * e);                 // LeakyReLU(0.2)
            float ex = __expf(e - m);
            float p = a ? ex : 0.f;
            l += p;
            unsigned long long p2 = pack2(p);
            const ulonglong2* w2 =
                reinterpret_cast<const ulonglong2*>(whs + (h * 64 + j) * 64);
#pragma unroll
            for (int c = 0; c < 16; c++) {
                ulonglong2 v = w2[c];
                fma2(acc2[2 * c], v.x, p2);
                fma2(acc2[2 * c + 1], v.y, p2);
            }
        }
        cp_wait0();
        __syncthreads();
    }

    // ---- epilogue: combine 4 j-quarter partials per (head,row) ----
    float* part = smem;                 // [3][H*32][68]
    float* lbuf = smem + LBUF_OFF;      // [3][128]
    float* redB = smem + REDB_OFF;      // [H][32][64] for AVG

    if (g > 0) {
        float* row = part + ((g - 1) * 128 + h * 32 + lane) * PART_STRIDE;
#pragma unroll
        for (int c = 0; c < 32; c++)
            reinterpret_cast<float2*>(row)[c] = *reinterpret_cast<float2*>(&acc2[c]);
        lbuf[(g - 1) * 128 + h * 32 + lane] = l;
    }
    __syncthreads();

    if (g == 0) {
        const float* r0 = part + (0 * 128 + h * 32 + lane) * PART_STRIDE;
        const float* r1 = part + (1 * 128 + h * 32 + lane) * PART_STRIDE;
        const float* r2 = part + (2 * 128 + h * 32 + lane) * PART_STRIDE;
        l += lbuf[0 * 128 + h * 32 + lane] + lbuf[1 * 128 + h * 32 + lane] +
             lbuf[2 * 128 + h * 32 + lane];
        float inv = 1.0f / fmaxf(l, 1e-30f);
        float* dst = AVG ? (redB + (h * 32 + lane) * 64)
                         : (g_h1 + (size_t)i * (H * D) + h * D);
#pragma unroll
        for (int c = 0; c < 16; c++) {
            float2 a0v = *reinterpret_cast<float2*>(&acc2[2 * c]);
            float2 a1v = *reinterpret_cast<float2*>(&acc2[2 * c + 1]);
            float4 b0 = reinterpret_cast<const float4*>(r0)[c];
            float4 b1 = reinterpret_cast<const float4*>(r1)[c];
            float4 b2 = reinterpret_cast<const float4*>(r2)[c];
            float4 v;
            v.x = elu_f((a0v.x + b0.x + b1.x + b2.x) * inv);
            v.y = elu_f((a0v.y + b0.y + b1.y + b2.y) * inv);
            v.z = elu_f((a1v.x + b0.z + b1.z + b2.z) * inv);
            v.w = elu_f((a1v.y + b0.w + b1.w + b2.w) * inv);
            reinterpret_cast<float4*>(dst)[c] = v;
        }
    }

    if (AVG) {
        __syncthreads();
        for (int idx = tid; idx < ROWS_PER_BLK * D; idx += 512) {
            int r = idx >> 6, k = idx & 63;
            float s = 0.25f * (redB[(0 * 32 + r) * 64 + k] + redB[(1 * 32 + r) * 64 + k] +
                               redB[(2 * 32 + r) * 64 + k] + redB[(3 * 32 + r) * 64 + k]);
            out[(rowbase + r) * D + k] = s;
        }
    }
}

// ---------------- launch ----------------
extern "C" void kernel_launch(void* const* d_in, const int* in_sizes, int n_in,
                              void* d_out, int out_size) {
    const float* x = (const float*)d_in[0];
    const int* adj = (const int*)d_in[1];
    const float* W0 = (const float*)d_in[2];
    const float* a0 = (const float*)d_in[3];
    const float* W1 = (const float*)d_in[4];
    const float* a1 = (const float*)d_in[5];
    float* out = (float*)d_out;

    cudaFuncSetAttribute(k_attn<false>, cudaFuncAttributeMaxDynamicSharedMemorySize,
                         ATTN_SMEM);
    cudaFuncSetAttribute(k_attn<true>, cudaFuncAttributeMaxDynamicSharedMemorySize,
                         ATTN_SMEM);
    cudaFuncSetAttribute(k_wh1, cudaFuncAttributeMaxDynamicSharedMemorySize, WH1_SMEM);

    // layer 0
    k_wh0<<<dim3(N_NODES / 8, H), 64>>>(x, W0, a0);
    k_maxfd<<<H, 256>>>();
    k_attn<false><<<N_NODES / ROWS_PER_BLK, 512, ATTN_SMEM>>>(adj, nullptr);

    // layer 1
    k_wh1<<<dim3(N_NODES / 64, H), 256, WH1_SMEM>>>(W1, a1);
    k_maxfd<<<H, 256>>>();
    k_attn<true><<<N_NODES / ROWS_PER_BLK, 512, ATTN_SMEM>>>(adj, out);
}